// round 6
// baseline (speedup 1.0000x reference)
#include <cuda_runtime.h>
#include <cstdint>

#define NGROUP 80
#define BEX 8
#define NPG 1024
#define MCENT 512
#define NTHR 512
#define MAXIT 300
#define TOLF 1e-3f

typedef unsigned long long u64;

// ---------------- device globals (no allocation allowed) ----------------
__device__ int g_flags[MAXIT + 1];
__device__ unsigned int g_bar_count;   // returns to 0 after each barrier
__device__ unsigned int g_bar_gen;     // monotonically increasing across replays (safe)

// ---------------- threefry2x32 (exact JAX PRNG, partitionable scheme) ----------------
__device__ __forceinline__ uint32_t rotl32(uint32_t x, int d) { return (x << d) | (x >> (32 - d)); }

__device__ __forceinline__ void tf2x32(uint32_t k0, uint32_t k1, uint32_t x0, uint32_t x1,
                                       uint32_t& o0, uint32_t& o1) {
    uint32_t ks0 = k0, ks1 = k1, ks2 = k0 ^ k1 ^ 0x1BD11BDAu;
#define RND(r) { x0 += x1; x1 = rotl32(x1, r); x1 ^= x0; }
    x0 += ks0; x1 += ks1;
    RND(13) RND(15) RND(26) RND(6)   x0 += ks1; x1 += ks2 + 1u;
    RND(17) RND(29) RND(16) RND(24)  x0 += ks2; x1 += ks0 + 2u;
    RND(13) RND(15) RND(26) RND(6)   x0 += ks0; x1 += ks1 + 3u;
    RND(17) RND(29) RND(16) RND(24)  x0 += ks1; x1 += ks2 + 4u;
    RND(13) RND(15) RND(26) RND(6)   x0 += ks2; x1 += ks0 + 5u;
#undef RND
    o0 = x0; o1 = x1;
}

// starts[g] = jax.random.randint(key(1), (80,), 0, 1024)[g], partitionable threefry:
//   k2 = tf((0,1),(0,1));  bits_g = xor-fold(tf(k2,(0,g)));  start = bits_g % 1024
__device__ __forceinline__ int jax_start(int gidx) {
    uint32_t c0, c1, o0, o1;
    tf2x32(0u, 1u, 0u, 1u, c0, c1);
    tf2x32(c0, c1, 0u, (uint32_t)gidx, o0, o1);
    return (int)((o0 ^ o1) & 1023u);
}

// ---------------- grid barrier (80 blocks, all co-resident) ----------------
__device__ void grid_barrier() {
    __syncthreads();
    if (threadIdx.x == 0) {
        volatile unsigned int* vgen = &g_bar_gen;
        unsigned int gen = *vgen;
        __threadfence();
        unsigned int ticket = atomicAdd(&g_bar_count, 1u);
        if (ticket == NGROUP - 1) {
            g_bar_count = 0u;
            __threadfence();
            atomicAdd(&g_bar_gen, 1u);
        } else {
            while (*vgen == gen) { __nanosleep(32); }
        }
        __threadfence();
    }
    __syncthreads();
}

__device__ __forceinline__ float sq3(float a, float b, float c) {
    // ((a*a + b*b) + c*c), non-fused (reference-critical math)
    return __fadd_rn(__fadd_rn(__fmul_rn(a, a), __fmul_rn(b, b)), __fmul_rn(c, c));
}

// ---------------- packed f32x2 helpers ----------------
__device__ __forceinline__ void pack2(float a, float b, u64& r) {
    asm("mov.b64 %0, {%1,%2};" : "=l"(r) : "f"(a), "f"(b));
}
__device__ __forceinline__ void unpack2(u64 v, float& lo, float& hi) {
    asm("mov.b64 {%0,%1}, %2;" : "=f"(lo), "=f"(hi) : "l"(v));
}
__device__ __forceinline__ u64 fma2(u64 a, u64 b, u64 c) {
    u64 d; asm("fma.rn.f32x2 %0, %1, %2, %3;" : "=l"(d) : "l"(a), "l"(b), "l"(c)); return d;
}

// ---------------- main persistent kernel: FPS + k-means + score ----------------
__global__ void __launch_bounds__(NTHR, 1)
kmeans_kernel(const float* __restrict__ pos, float* __restrict__ out, int out_size) {
    __shared__ float4   sP[NPG];          // points                             16384 B
    __shared__ float4   sC[MCENT];        // centroids (x,y,z,|c|^2)             8192 B
    // pair-packed SoA for assign: [p*4+0]=(-2cx)2 [p*4+1]=(-2cy)2 [p*4+2]=(-2cz)2 [p*4+3]=(c2)2
    __shared__ u64      sC2[MCENT * 2];   //                                     8192 B
    __shared__ uint8_t  whist[32][MCENT]; // rows 0-15: A-points, 16-31: B      16384 B
    __shared__ uint16_t sortIdx[NPG];     // cluster-sorted point indices        2048 B
    __shared__ uint16_t sCnt[MCENT];
    __shared__ uint16_t sOff[MCENT];
    __shared__ uint32_t sWsum[16];
    __shared__ uint32_t redV[2][16];
    __shared__ uint32_t redI[2][16];
    __shared__ float    redF[16];
    __shared__ float    sScore;
    __shared__ int      sStart;

    const int g = blockIdx.x;
    const int t = threadIdx.x;
    const int b = g & (BEX - 1);           // group g = r*B + b  ->  example b
    const float* pb = pos + (size_t)b * NPG * 3;

    // two points per thread: A = t, B = t + 512
    const float pxA = pb[t * 3 + 0], pyA = pb[t * 3 + 1], pzA = pb[t * 3 + 2];
    const float pxB = pb[(t + NTHR) * 3 + 0], pyB = pb[(t + NTHR) * 3 + 1], pzB = pb[(t + NTHR) * 3 + 2];
    sP[t]        = make_float4(pxA, pyA, pzA, 0.f);
    sP[t + NTHR] = make_float4(pxB, pyB, pzB, 0.f);
    if (t == NTHR - 1) sStart = jax_start(g);    // merged starts kernel (exact)
    __syncthreads();

    const int wid = t >> 5, lane = t & 31;
    float* sCf = (float*)sC2;             // float view: [p*8 + field*2 + half]

    // ================= FPS init (R4-identical math & structure) =================
    int last = sStart;
    float mindA = __int_as_float(0x7f800000);
    float mindB = __int_as_float(0x7f800000);
    for (int k = 0; k < MCENT; ++k) {
        float4 q = sP[last];                   // uniform broadcast
        if (t == 0) {
            float c2 = sq3(q.x, q.y, q.z);
            sC[k] = make_float4(q.x, q.y, q.z, c2);
            int p = k >> 1, h = k & 1;         // packed layout for assign
            sCf[p * 8 + 0 + h] = __fmul_rn(-2.0f, q.x);
            sCf[p * 8 + 2 + h] = __fmul_rn(-2.0f, q.y);
            sCf[p * 8 + 4 + h] = __fmul_rn(-2.0f, q.z);
            sCf[p * 8 + 6 + h] = c2;
        }
        {
            float dx = __fsub_rn(pxA, q.x), dy = __fsub_rn(pyA, q.y), dz = __fsub_rn(pzA, q.z);
            mindA = fminf(mindA, sq3(dx, dy, dz));
        }
        {
            float dx = __fsub_rn(pxB, q.x), dy = __fsub_rn(pyB, q.y), dz = __fsub_rn(pzB, q.z);
            mindB = fminf(mindB, sq3(dx, dy, dz));
        }
        // argmax(mind), FIRST-index tie-break: value-max + min-index-among-max.
        uint32_t bA = __float_as_uint(mindA);  // positive-float bits monotonic
        uint32_t bB = __float_as_uint(mindB);
        uint32_t val = (bB > bA) ? bB : bA;
        uint32_t idx = (bB > bA) ? (uint32_t)(t + NTHR) : (uint32_t)t;  // tie -> A (smaller idx)
        uint32_t wm  = __reduce_max_sync(0xffffffffu, val);
        uint32_t cnd = (val == wm) ? idx : 0xFFFFu;
        uint32_t wix = __reduce_min_sync(0xffffffffu, cnd);
        int par = k & 1;
        if (lane == 0) { redV[par][wid] = wm; redI[par][wid] = wix; }
        __syncthreads();
        uint32_t v  = (lane < 16) ? redV[par][lane] : 0u;
        uint32_t gm = __reduce_max_sync(0xffffffffu, v);
        uint32_t c2m = (lane < 16 && v == gm) ? redI[par][lane] : 0xFFFFu;
        last = (int)__reduce_min_sync(0xffffffffu, c2m);   // smallest global index
    }
    __syncthreads();

    // point coords packed once for the assign loop
    u64 px2A, py2A, pz2A, px2B, py2B, pz2B;
    pack2(pxA, pxA, px2A); pack2(pyA, pyA, py2A); pack2(pzA, pzA, pz2A);
    pack2(pxB, pxB, px2B); pack2(pyB, pyB, py2B); pack2(pzB, pzB, pz2B);
    const ulonglong2* sC2v = (const ulonglong2*)sC2;

    // ================= k-means loop (global lockstep) =================
    int bjA = 0, bjB = 0;
    for (int iter = 0; iter < MAXIT; ++iter) {
        // ---- assign: argmin_j (c2 + px*(-2cx) + py*(-2cy) + pz*(-2cz)) ----
        // two parity chains per point to halve the loop-carried compare latency
        float bA0 = __int_as_float(0x7f800000), bA1 = __int_as_float(0x7f800000);
        float bB0 = __int_as_float(0x7f800000), bB1 = __int_as_float(0x7f800000);
        int jA0 = 0, jA1 = 0, jB0 = 0, jB1 = 0;
        #pragma unroll 8
        for (int p = 0; p < MCENT / 2; ++p) {
            ulonglong2 m0 = sC2v[2 * p];       // (-2cx)2, (-2cy)2
            ulonglong2 m1 = sC2v[2 * p + 1];   // (-2cz)2, (c2)2
            u64 accA = fma2(pz2A, m1.x, fma2(py2A, m0.y, fma2(px2A, m0.x, m1.y)));
            u64 accB = fma2(pz2B, m1.x, fma2(py2B, m0.y, fma2(px2B, m0.x, m1.y)));
            float alo, ahi; unpack2(accA, alo, ahi);
            float blo, bhi; unpack2(accB, blo, bhi);
            if ((p & 1) == 0) {
                if (alo < bA0) { bA0 = alo; jA0 = 2 * p; }
                if (ahi < bA0) { bA0 = ahi; jA0 = 2 * p + 1; }
                if (blo < bB0) { bB0 = blo; jB0 = 2 * p; }
                if (bhi < bB0) { bB0 = bhi; jB0 = 2 * p + 1; }
            } else {
                if (alo < bA1) { bA1 = alo; jA1 = 2 * p; }
                if (ahi < bA1) { bA1 = ahi; jA1 = 2 * p + 1; }
                if (blo < bB1) { bB1 = blo; jB1 = 2 * p; }
                if (bhi < bB1) { bB1 = bhi; jB1 = 2 * p + 1; }
            }
        }
        // exact merge: value first, then smaller index (first-occurrence semantics)
        bjA = jA0;
        if (bA1 < bA0 || (bA1 == bA0 && jA1 < jA0)) bjA = jA1;
        bjB = jB0;
        if (bB1 < bB0 || (bB1 == bB0 && jB1 < jB0)) bjB = jB1;

        // ---- deterministic stable counting sort of points by cluster ----
        ((uint4*)whist)[t * 2]     = make_uint4(0u, 0u, 0u, 0u);   // zero 16KB
        ((uint4*)whist)[t * 2 + 1] = make_uint4(0u, 0u, 0u, 0u);
        __syncthreads();

        uint32_t below = (1u << lane) - 1u;
        uint32_t mmA = __match_any_sync(0xffffffffu, (uint32_t)bjA);
        int riwA = __popc(mmA & below);
        if (riwA == 0) whist[wid][bjA] = (uint8_t)__popc(mmA);
        uint32_t mmB = __match_any_sync(0xffffffffu, (uint32_t)bjB);
        int riwB = __popc(mmB & below);
        if (riwB == 0) whist[16 + wid][bjB] = (uint8_t)__popc(mmB);
        __syncthreads();

        // per-cluster exclusive prefix over the 32 rows (in place) + counts
        uint32_t run = 0;
        #pragma unroll
        for (int w = 0; w < 32; ++w) {
            uint32_t v = whist[w][t];
            whist[w][t] = (uint8_t)run;
            run += v;
        }
        sCnt[t] = (uint16_t)run;

        // block-wide exclusive prefix sum over the 512 counts (16 warps)
        uint32_t x = run;
        #pragma unroll
        for (int o = 1; o < 32; o <<= 1) {
            uint32_t y = __shfl_up_sync(0xffffffffu, x, o);
            if (lane >= o) x += y;
        }
        uint32_t exclInWarp = x - run;
        if (lane == 31) sWsum[wid] = x;
        __syncthreads();
        if (wid == 0) {
            uint32_t wv = (lane < 16) ? sWsum[lane] : 0u;
            uint32_t xx = wv;
            #pragma unroll
            for (int o = 1; o < 16; o <<= 1) {
                uint32_t y = __shfl_up_sync(0xffffffffu, xx, o);
                if (lane >= o) xx += y;
            }
            if (lane < 16) sWsum[lane] = xx - wv;
        }
        __syncthreads();
        sOff[t] = (uint16_t)(sWsum[wid] + exclInWarp);
        __syncthreads();

        // scatter point indices; ascending-index order preserved per cluster
        {
            uint32_t rkA = (uint32_t)sOff[bjA] + whist[wid][bjA] + (uint32_t)riwA;
            sortIdx[rkA] = (uint16_t)t;
            uint32_t rkB = (uint32_t)sOff[bjB] + whist[16 + wid][bjB] + (uint32_t)riwB;
            sortIdx[rkB] = (uint16_t)(t + NTHR);
        }
        __syncthreads();

        // per-cluster ordered fold + centroid update + convergence
        int moved = 0;
        {
            uint32_t n = sCnt[t], base = sOff[t];
            float sx = 0.f, sy = 0.f, sz = 0.f;
            for (uint32_t k2 = 0; k2 < n; ++k2) {
                float4 p = sP[sortIdx[base + k2]];
                sx = __fadd_rn(sx, p.x);
                sy = __fadd_rn(sy, p.y);
                sz = __fadd_rn(sz, p.z);
            }
            float4 oc = sC[t];               // conflict-free read of old centroid
            float cntf = (float)n;
            float nx, ny, nz;
            if (n > 0) {
                nx = __fdiv_rn(sx, cntf); ny = __fdiv_rn(sy, cntf); nz = __fdiv_rn(sz, cntf);
            } else {
                nx = oc.x; ny = oc.y; nz = oc.z;
            }
            float dx = __fsub_rn(oc.x, nx), dy = __fsub_rn(oc.y, ny), dz = __fsub_rn(oc.z, nz);
            moved = !(sqrtf(sq3(dx, dy, dz)) < TOLF);
            float c2n = sq3(nx, ny, nz);
            sC[t] = make_float4(nx, ny, nz, c2n);
            int pp = t >> 1, h = t & 1;       // packed layout for next assign
            sCf[pp * 8 + 0 + h] = __fmul_rn(-2.0f, nx);
            sCf[pp * 8 + 2 + h] = __fmul_rn(-2.0f, ny);
            sCf[pp * 8 + 4 + h] = __fmul_rn(-2.0f, nz);
            sCf[pp * 8 + 6 + h] = c2n;
        }
        int any = __syncthreads_or(moved);
        if (t == 0 && any) atomicOr(&g_flags[iter], 1);
        grid_barrier();
        int notdone = *((volatile int*)&g_flags[iter]);
        if (!notdone) break;   // all blocks agree -> same iteration count everywhere
    }

    // ================= score: L1 to assigned (final) centroids =================
    {
        float4 ca = sC[bjA];
        float4 cb = sC[bjB];
        float s = fabsf(pxA - ca.x) + fabsf(pyA - ca.y) + fabsf(pzA - ca.z)
                + fabsf(pxB - cb.x) + fabsf(pyB - cb.y) + fabsf(pzB - cb.z);
        #pragma unroll
        for (int off = 16; off > 0; off >>= 1)
            s += __shfl_down_sync(0xffffffffu, s, off);
        if (lane == 0) redF[wid] = s;
        __syncthreads();
        if (wid == 0) {
            float v = (lane < 16) ? redF[lane] : 0.f;
            #pragma unroll
            for (int off = 8; off > 0; off >>= 1)
                v += __shfl_down_sync(0xffffffffu, v, off);
            if (lane == 0) sScore = v;
        }
        __syncthreads();
    }

    // ================= outputs: [classification | centroids | scores] =================
    int ci = g * NPG + t;
    if (ci < out_size) out[ci] = (float)bjA;
    int ci2 = g * NPG + NTHR + t;
    if (ci2 < out_size) out[ci2] = (float)bjB;
    {
        int base = NGROUP * NPG + g * (MCENT * 3) + t * 3;
        if (base + 2 < out_size) {
            float4 cs = sC[t];
            out[base + 0] = cs.x;
            out[base + 1] = cs.y;
            out[base + 2] = cs.z;
        }
    }
    if (t == 0) {
        int si = NGROUP * NPG + NGROUP * MCENT * 3 + g;
        if (si < out_size) out[si] = sScore;
    }
}

extern "C" void kernel_launch(void* const* d_in, const int* in_sizes, int n_in,
                              void* d_out, int out_size) {
    const float* pos = (const float*)d_in[0];
    void* flagsAddr = nullptr;
    cudaGetSymbolAddress(&flagsAddr, g_flags);
    cudaMemsetAsync(flagsAddr, 0, sizeof(int) * (MAXIT + 1), 0);
    kmeans_kernel<<<NGROUP, NTHR>>>(pos, (float*)d_out, out_size);
}